// round 1
// baseline (speedup 1.0000x reference)
#include <cuda_runtime.h>
#include <math.h>

#define N 1024
#define D 128
#define SPARSE_K 32

// ---------------- device scratch (no allocations allowed) ----------------
__device__ float g_Q[N * D];
__device__ float g_K[N * D];
__device__ float g_A[N * D];   // z @ W1[:D] + b1   (b1 folded here)
__device__ float g_B[N * D];   // z @ W1[D:]
__device__ float g_S[(size_t)N * N];

__device__ __forceinline__ float neg_inf() { return __int_as_float(0xff800000); }

__device__ __forceinline__ float gelu_exact(float x) {
    // jax.nn.gelu(approximate=False) = 0.5*x*(1+erf(x/sqrt(2)))
    return 0.5f * x * (1.0f + erff(x * 0.70710678118654752f));
}

// =====================================================================
// Kernel 1: out[64x128 tile] = z[64x128] @ W[128x128] (+ bias)
// which: 0->g_Q, 1->g_K, 2->g_A, 3->g_B
// =====================================================================
__global__ __launch_bounds__(256) void proj_kernel(const float* __restrict__ z,
                                                   const float* __restrict__ W,
                                                   const float* __restrict__ bias,
                                                   int which)
{
    __shared__ float zs[64][33];   // [row][k-chunk], padded
    __shared__ float ws[32][128];  // [k-chunk][col]

    float* out = (which == 0) ? g_Q : (which == 1) ? g_K : (which == 2) ? g_A : g_B;

    int tid = threadIdx.x;
    int tx = tid & 31;        // col lane: cols tx + 32*cc
    int ty = tid >> 5;        // row group: rows ty*8 .. ty*8+7
    int row0 = blockIdx.x * 64;

    float acc[8][4];
#pragma unroll
    for (int r = 0; r < 8; r++)
#pragma unroll
        for (int c = 0; c < 4; c++) acc[r][c] = 0.0f;

    for (int kc = 0; kc < D; kc += 32) {
        for (int idx = tid; idx < 64 * 32; idx += 256) {
            int r = idx >> 5, c = idx & 31;
            zs[r][c] = z[(row0 + r) * D + kc + c];
        }
        for (int idx = tid; idx < 32 * 128; idx += 256) {
            int r = idx >> 7, c = idx & 127;
            ws[r][c] = W[(kc + r) * D + c];
        }
        __syncthreads();
#pragma unroll 8
        for (int k = 0; k < 32; k++) {
            float w0 = ws[k][tx];
            float w1 = ws[k][tx + 32];
            float w2 = ws[k][tx + 64];
            float w3 = ws[k][tx + 96];
#pragma unroll
            for (int r = 0; r < 8; r++) {
                float a = zs[ty * 8 + r][k];
                acc[r][0] = fmaf(a, w0, acc[r][0]);
                acc[r][1] = fmaf(a, w1, acc[r][1]);
                acc[r][2] = fmaf(a, w2, acc[r][2]);
                acc[r][3] = fmaf(a, w3, acc[r][3]);
            }
        }
        __syncthreads();
    }

    float b0 = 0.f, b1 = 0.f, b2 = 0.f, b3 = 0.f;
    if (bias) { b0 = bias[tx]; b1 = bias[tx + 32]; b2 = bias[tx + 64]; b3 = bias[tx + 96]; }
#pragma unroll
    for (int r = 0; r < 8; r++) {
        int row = row0 + ty * 8 + r;
        out[row * D + tx      ] = acc[r][0] + b0;
        out[row * D + tx + 32 ] = acc[r][1] + b1;
        out[row * D + tx + 64 ] = acc[r][2] + b2;
        out[row * D + tx + 96 ] = acc[r][3] + b3;
    }
}

// =====================================================================
// Kernel 2: S[i][j] = (Q_i . K_j) * (1/sqrt(D)) * exp(-sd[i][j])
// 64x64 tiles, k chunked by 64
// =====================================================================
__global__ __launch_bounds__(256) void attn_kernel(const float* __restrict__ sd)
{
    __shared__ float Qs[64][65];
    __shared__ float Ks[64][65];

    int tid = threadIdx.x;
    int tx = tid & 15;         // j lanes: j = j0 + tx + 16*cj
    int ty = tid >> 4;         // i group: i = i0 + ty*4 + ri
    int i0 = blockIdx.y * 64;
    int j0 = blockIdx.x * 64;

    float acc[4][4];
#pragma unroll
    for (int a = 0; a < 4; a++)
#pragma unroll
        for (int b = 0; b < 4; b++) acc[a][b] = 0.0f;

    for (int kc = 0; kc < D; kc += 64) {
        for (int idx = tid; idx < 64 * 64; idx += 256) {
            int r = idx >> 6, c = idx & 63;
            Qs[r][c] = g_Q[(i0 + r) * D + kc + c];
            Ks[r][c] = g_K[(j0 + r) * D + kc + c];
        }
        __syncthreads();
#pragma unroll 8
        for (int k = 0; k < 64; k++) {
            float qv[4], kv[4];
#pragma unroll
            for (int ri = 0; ri < 4; ri++) qv[ri] = Qs[ty * 4 + ri][k];
#pragma unroll
            for (int cj = 0; cj < 4; cj++) kv[cj] = Ks[tx + cj * 16][k];
#pragma unroll
            for (int ri = 0; ri < 4; ri++)
#pragma unroll
                for (int cj = 0; cj < 4; cj++)
                    acc[ri][cj] = fmaf(qv[ri], kv[cj], acc[ri][cj]);
        }
        __syncthreads();
    }

    const float SCALE = 0.08838834764831845f;  // 1/sqrt(128) / TEMPERATURE
#pragma unroll
    for (int ri = 0; ri < 4; ri++) {
        int i = i0 + ty * 4 + ri;
#pragma unroll
        for (int cj = 0; cj < 4; cj++) {
            int j = j0 + tx + cj * 16;
            size_t idx = (size_t)i * N + j;
            g_S[idx] = acc[ri][cj] * SCALE * __expf(-sd[idx]);
        }
    }
}

// =====================================================================
// Kernel 3: row softmax + top-32 scatter -> adjacency (d_out[0 : N*N])
// one block (256 threads) per row; each thread owns 4 values
// =====================================================================
__device__ __forceinline__ float block_reduce_max(float x, float* red) {
#pragma unroll
    for (int o = 16; o; o >>= 1) x = fmaxf(x, __shfl_xor_sync(0xffffffffu, x, o));
    int w = threadIdx.x >> 5, l = threadIdx.x & 31;
    if (l == 0) red[w] = x;
    __syncthreads();
    if (w == 0) {
        float y = (l < 8) ? red[l] : neg_inf();
#pragma unroll
        for (int o = 4; o; o >>= 1) y = fmaxf(y, __shfl_xor_sync(0xffffffffu, y, o));
        if (l == 0) red[8] = y;
    }
    __syncthreads();
    float r = red[8];
    __syncthreads();
    return r;
}

__device__ __forceinline__ float block_reduce_sum(float x, float* red) {
#pragma unroll
    for (int o = 16; o; o >>= 1) x += __shfl_xor_sync(0xffffffffu, x, o);
    int w = threadIdx.x >> 5, l = threadIdx.x & 31;
    if (l == 0) red[w] = x;
    __syncthreads();
    if (w == 0) {
        float y = (l < 8) ? red[l] : 0.0f;
#pragma unroll
        for (int o = 4; o; o >>= 1) y += __shfl_xor_sync(0xffffffffu, y, o);
        if (l == 0) red[8] = y;
    }
    __syncthreads();
    float r = red[8];
    __syncthreads();
    return r;
}

__global__ __launch_bounds__(256) void softmax_topk_kernel(float* __restrict__ out_adj)
{
    __shared__ float red[9];
    int row = blockIdx.x;
    int tid = threadIdx.x;
    const float* s = g_S + (size_t)row * N;

    float v[4];
#pragma unroll
    for (int q = 0; q < 4; q++) v[q] = s[tid + q * 256];

    float m = fmaxf(fmaxf(v[0], v[1]), fmaxf(v[2], v[3]));
    m = block_reduce_max(m, red);

    float p[4], ls = 0.0f;
#pragma unroll
    for (int q = 0; q < 4; q++) { p[q] = __expf(v[q] - m); ls += p[q]; }
    float Z = block_reduce_sum(ls, red);

    // find 32nd-largest raw score (same ordering as softmax probs)
    float w[4];
#pragma unroll
    for (int q = 0; q < 4; q++) w[q] = v[q];
    float thresh = neg_inf();
    for (int it = 0; it < SPARSE_K; it++) {
        float lm = fmaxf(fmaxf(w[0], w[1]), fmaxf(w[2], w[3]));
        float gm = block_reduce_max(lm, red);
#pragma unroll
        for (int q = 0; q < 4; q++) if (w[q] == gm) w[q] = neg_inf();
        thresh = gm;
    }

    float invZ = __fdividef(1.0f, Z);
#pragma unroll
    for (int q = 0; q < 4; q++) {
        int j = tid + q * 256;
        out_adj[(size_t)row * N + j] = (v[q] >= thresh) ? p[q] * invZ : 0.0f;
    }
}

// =====================================================================
// Kernel 4 (dominant): signaling_type[i][j][:] =
//   softmax( sum_d gelu(a_i[d] + b_j[d]) * W2[d,:] + b2 )
// 64x64 pair tiles, 4i x 4j per thread, d chunked by 64
// =====================================================================
__global__ __launch_bounds__(256, 2) void pair_kernel(const float* __restrict__ W2,
                                                      const float* __restrict__ b2,
                                                      float* __restrict__ out)
{
    __shared__ float As[64][65];
    __shared__ float Bs[64][65];
    __shared__ float w2s[D * 3];
    __shared__ float b2s[3];

    int tid = threadIdx.x;
    int tx = tid & 15;          // j = j0 + tx + 16*cj
    int ty = tid >> 4;          // i = i0 + ty*4 + ri
    int i0 = blockIdx.y * 64;
    int j0 = blockIdx.x * 64;

    for (int idx = tid; idx < D * 3; idx += 256) w2s[idx] = W2[idx];
    if (tid < 3) b2s[tid] = b2[tid];

    float acc[4][4][3];
#pragma unroll
    for (int a = 0; a < 4; a++)
#pragma unroll
        for (int b = 0; b < 4; b++)
#pragma unroll
            for (int c = 0; c < 3; c++) acc[a][b][c] = 0.0f;

    for (int kc = 0; kc < D; kc += 64) {
        for (int idx = tid; idx < 64 * 64; idx += 256) {
            int r = idx >> 6, c = idx & 63;
            As[r][c] = g_A[(i0 + r) * D + kc + c];
            Bs[r][c] = g_B[(j0 + r) * D + kc + c];
        }
        __syncthreads();
#pragma unroll 4
        for (int k = 0; k < 64; k++) {
            int d = kc + k;
            float w0 = w2s[d * 3 + 0];
            float w1 = w2s[d * 3 + 1];
            float w2v = w2s[d * 3 + 2];
            float av[4], bv[4];
#pragma unroll
            for (int ri = 0; ri < 4; ri++) av[ri] = As[ty * 4 + ri][k];
#pragma unroll
            for (int cj = 0; cj < 4; cj++) bv[cj] = Bs[tx + cj * 16][k];
#pragma unroll
            for (int ri = 0; ri < 4; ri++) {
#pragma unroll
                for (int cj = 0; cj < 4; cj++) {
                    float g = gelu_exact(av[ri] + bv[cj]);
                    acc[ri][cj][0] = fmaf(g, w0,  acc[ri][cj][0]);
                    acc[ri][cj][1] = fmaf(g, w1,  acc[ri][cj][1]);
                    acc[ri][cj][2] = fmaf(g, w2v, acc[ri][cj][2]);
                }
            }
        }
        __syncthreads();
    }

    const size_t OFF = (size_t)N * N;
#pragma unroll
    for (int ri = 0; ri < 4; ri++) {
        int i = i0 + ty * 4 + ri;
#pragma unroll
        for (int cj = 0; cj < 4; cj++) {
            int j = j0 + tx + cj * 16;
            float l0 = acc[ri][cj][0] + b2s[0];
            float l1 = acc[ri][cj][1] + b2s[1];
            float l2 = acc[ri][cj][2] + b2s[2];
            float mm = fmaxf(l0, fmaxf(l1, l2));
            float e0 = __expf(l0 - mm);
            float e1 = __expf(l1 - mm);
            float e2 = __expf(l2 - mm);
            float inv = __fdividef(1.0f, e0 + e1 + e2);
            size_t base = OFF + ((size_t)i * N + j) * 3;
            out[base + 0] = e0 * inv;
            out[base + 1] = e1 * inv;
            out[base + 2] = e2 * inv;
        }
    }
}

// =====================================================================
// launch
// =====================================================================
extern "C" void kernel_launch(void* const* d_in, const int* in_sizes, int n_in,
                              void* d_out, int out_size)
{
    const float* z   = (const float*)d_in[0];
    const float* sd  = (const float*)d_in[1];
    const float* Wq  = (const float*)d_in[2];
    const float* bq  = (const float*)d_in[3];
    const float* Wk  = (const float*)d_in[4];
    const float* bk  = (const float*)d_in[5];
    const float* W1  = (const float*)d_in[6];
    const float* b1  = (const float*)d_in[7];
    const float* W2  = (const float*)d_in[8];
    const float* b2  = (const float*)d_in[9];
    float* out = (float*)d_out;

    (void)in_sizes; (void)n_in; (void)out_size;

    proj_kernel<<<16, 256>>>(z, Wq, bq, 0);
    proj_kernel<<<16, 256>>>(z, Wk, bk, 1);
    proj_kernel<<<16, 256>>>(z, W1, b1, 2);           // a + b1 folded
    proj_kernel<<<16, 256>>>(z, W1 + D * D, nullptr, 3);

    attn_kernel<<<dim3(16, 16), 256>>>(sd);
    softmax_topk_kernel<<<N, 256>>>(out);              // adjacency -> out[0 : N*N]

    pair_kernel<<<dim3(16, 16), 256>>>(W2, b2, out);   // signaling -> out[N*N : 4*N*N]
}

// round 2
// speedup vs baseline: 2.4308x; 2.4308x over previous
#include <cuda_runtime.h>
#include <math.h>

#define N 1024
#define D 128
#define SPARSE_K 32

// ---------------- device scratch (no allocations allowed) ----------------
__device__ float g_Q[N * D];
__device__ float g_K[N * D];
__device__ float g_A[N * D];   // z @ W1[:D] + b1   (b1 folded here)
__device__ float g_B[N * D];   // z @ W1[D:]
__device__ float g_S[(size_t)N * N];

__device__ __forceinline__ float neg_inf() { return __int_as_float(0xff800000); }

// tanh-form GELU using HW MUFU.TANH: 6 FMA-class + 1 MUFU
__device__ __forceinline__ float gelu_fast(float x) {
    float u  = x * x;
    float t  = x * fmaf(0.044715f, u, 1.0f);
    float y  = 0.7978845608028654f * t;
    float th;
    asm("tanh.approx.f32 %0, %1;" : "=f"(th) : "f"(y));
    float hx = 0.5f * x;
    return fmaf(hx, th, hx);
}

// =====================================================================
// Kernel 1 (fused): [Q | K | A | B] = z @ [Wq | Wk | W1a | W1b] (+ bias)
// grid: x = 8 column tiles (2 per weight), y = 16 row tiles of 64
// block: 256 threads, 64x64 output tile, 4x4 per thread
// =====================================================================
__global__ __launch_bounds__(256) void proj_fused_kernel(
    const float* __restrict__ z,
    const float* __restrict__ Wq, const float* __restrict__ bq,
    const float* __restrict__ Wk, const float* __restrict__ bk,
    const float* __restrict__ W1, const float* __restrict__ b1)
{
    __shared__ __align__(16) float Zs[64][68];
    __shared__ __align__(16) float Ws[64][68];

    int ct = blockIdx.x;           // 0..7
    int which = ct >> 1;
    int j0 = (ct & 1) * 64;        // column offset within the 128-col weight
    int i0 = blockIdx.y * 64;

    const float* W; const float* bias; float* out;
    if (which == 0)      { W = Wq;         bias = bq;      out = g_Q; }
    else if (which == 1) { W = Wk;         bias = bk;      out = g_K; }
    else if (which == 2) { W = W1;         bias = b1;      out = g_A; }
    else                 { W = W1 + D * D; bias = nullptr; out = g_B; }

    int tid = threadIdx.x;
    int tx = tid & 15;             // j = j0 + tx + 16*cj
    int ty = tid >> 4;             // i = i0 + ty*4 + ri

    float acc[4][4];
#pragma unroll
    for (int a = 0; a < 4; a++)
#pragma unroll
        for (int b = 0; b < 4; b++) acc[a][b] = 0.0f;

    for (int kc = 0; kc < D; kc += 64) {
        // float4 loaders: 1024 float4 per array, 256 threads -> 4 iters each
#pragma unroll
        for (int it = 0; it < 4; it++) {
            int f = tid + it * 256;
            int r = f >> 4, c4 = f & 15;
            *(float4*)&Zs[r][c4 * 4] = *(const float4*)&z[(i0 + r) * D + kc + c4 * 4];
            *(float4*)&Ws[r][c4 * 4] = *(const float4*)&W[(kc + r) * D + j0 + c4 * 4];
        }
        __syncthreads();
#pragma unroll 8
        for (int k = 0; k < 64; k++) {
            float av[4], bv[4];
#pragma unroll
            for (int ri = 0; ri < 4; ri++) av[ri] = Zs[ty * 4 + ri][k];
#pragma unroll
            for (int cj = 0; cj < 4; cj++) bv[cj] = Ws[k][tx + cj * 16];
#pragma unroll
            for (int ri = 0; ri < 4; ri++)
#pragma unroll
                for (int cj = 0; cj < 4; cj++)
                    acc[ri][cj] = fmaf(av[ri], bv[cj], acc[ri][cj]);
        }
        __syncthreads();
    }

    float bb[4] = {0.f, 0.f, 0.f, 0.f};
    if (bias) {
#pragma unroll
        for (int cj = 0; cj < 4; cj++) bb[cj] = bias[j0 + tx + cj * 16];
    }
#pragma unroll
    for (int ri = 0; ri < 4; ri++) {
        int row = i0 + ty * 4 + ri;
#pragma unroll
        for (int cj = 0; cj < 4; cj++)
            out[row * D + j0 + tx + cj * 16] = acc[ri][cj] + bb[cj];
    }
}

// =====================================================================
// Kernel 2: S[i][j] = (Q_i . K_j) * (1/sqrt(D)) * exp(-sd[i][j])
// =====================================================================
__global__ __launch_bounds__(256) void attn_kernel(const float* __restrict__ sd)
{
    __shared__ __align__(16) float Qs[64][68];
    __shared__ __align__(16) float Ks[64][68];

    int tid = threadIdx.x;
    int tx = tid & 15;
    int ty = tid >> 4;
    int i0 = blockIdx.y * 64;
    int j0 = blockIdx.x * 64;

    float acc[4][4];
#pragma unroll
    for (int a = 0; a < 4; a++)
#pragma unroll
        for (int b = 0; b < 4; b++) acc[a][b] = 0.0f;

    for (int kc = 0; kc < D; kc += 64) {
#pragma unroll
        for (int it = 0; it < 4; it++) {
            int f = tid + it * 256;
            int r = f >> 4, c4 = f & 15;
            *(float4*)&Qs[r][c4 * 4] = *(const float4*)&g_Q[(i0 + r) * D + kc + c4 * 4];
            *(float4*)&Ks[r][c4 * 4] = *(const float4*)&g_K[(j0 + r) * D + kc + c4 * 4];
        }
        __syncthreads();
#pragma unroll 8
        for (int k = 0; k < 64; k++) {
            float qv[4], kv[4];
#pragma unroll
            for (int ri = 0; ri < 4; ri++) qv[ri] = Qs[ty * 4 + ri][k];
#pragma unroll
            for (int cj = 0; cj < 4; cj++) kv[cj] = Ks[tx + cj * 16][k];
#pragma unroll
            for (int ri = 0; ri < 4; ri++)
#pragma unroll
                for (int cj = 0; cj < 4; cj++)
                    acc[ri][cj] = fmaf(qv[ri], kv[cj], acc[ri][cj]);
        }
        __syncthreads();
    }

    const float SCALE = 0.08838834764831845f;  // 1/sqrt(128) / TEMPERATURE
#pragma unroll
    for (int ri = 0; ri < 4; ri++) {
        int i = i0 + ty * 4 + ri;
#pragma unroll
        for (int cj = 0; cj < 4; cj++) {
            int j = j0 + tx + cj * 16;
            size_t idx = (size_t)i * N + j;
            g_S[idx] = acc[ri][cj] * SCALE * __expf(-sd[idx]);
        }
    }
}

// =====================================================================
// Kernel 3: row softmax + top-32 scatter -> adjacency (d_out[0 : N*N])
// =====================================================================
__device__ __forceinline__ float block_reduce_max(float x, float* red) {
#pragma unroll
    for (int o = 16; o; o >>= 1) x = fmaxf(x, __shfl_xor_sync(0xffffffffu, x, o));
    int w = threadIdx.x >> 5, l = threadIdx.x & 31;
    if (l == 0) red[w] = x;
    __syncthreads();
    if (w == 0) {
        float y = (l < 8) ? red[l] : neg_inf();
#pragma unroll
        for (int o = 4; o; o >>= 1) y = fmaxf(y, __shfl_xor_sync(0xffffffffu, y, o));
        if (l == 0) red[8] = y;
    }
    __syncthreads();
    float r = red[8];
    __syncthreads();
    return r;
}

__device__ __forceinline__ float block_reduce_sum(float x, float* red) {
#pragma unroll
    for (int o = 16; o; o >>= 1) x += __shfl_xor_sync(0xffffffffu, x, o);
    int w = threadIdx.x >> 5, l = threadIdx.x & 31;
    if (l == 0) red[w] = x;
    __syncthreads();
    if (w == 0) {
        float y = (l < 8) ? red[l] : 0.0f;
#pragma unroll
        for (int o = 4; o; o >>= 1) y += __shfl_xor_sync(0xffffffffu, y, o);
        if (l == 0) red[8] = y;
    }
    __syncthreads();
    float r = red[8];
    __syncthreads();
    return r;
}

__global__ __launch_bounds__(256) void softmax_topk_kernel(float* __restrict__ out_adj)
{
    __shared__ float red[9];
    int row = blockIdx.x;
    int tid = threadIdx.x;
    const float* s = g_S + (size_t)row * N;

    float v[4];
#pragma unroll
    for (int q = 0; q < 4; q++) v[q] = s[tid + q * 256];

    float m = fmaxf(fmaxf(v[0], v[1]), fmaxf(v[2], v[3]));
    m = block_reduce_max(m, red);

    float p[4], ls = 0.0f;
#pragma unroll
    for (int q = 0; q < 4; q++) { p[q] = __expf(v[q] - m); ls += p[q]; }
    float Z = block_reduce_sum(ls, red);

    float w[4];
#pragma unroll
    for (int q = 0; q < 4; q++) w[q] = v[q];
    float thresh = neg_inf();
    for (int it = 0; it < SPARSE_K; it++) {
        float lm = fmaxf(fmaxf(w[0], w[1]), fmaxf(w[2], w[3]));
        float gm = block_reduce_max(lm, red);
#pragma unroll
        for (int q = 0; q < 4; q++) if (w[q] == gm) w[q] = neg_inf();
        thresh = gm;
    }

    float invZ = __fdividef(1.0f, Z);
#pragma unroll
    for (int q = 0; q < 4; q++) {
        int j = tid + q * 256;
        out_adj[(size_t)row * N + j] = (v[q] >= thresh) ? p[q] * invZ : 0.0f;
    }
}

// =====================================================================
// Kernel 4 (dominant): signaling_type[i][j][:] =
//   softmax( sum_d gelu(a_i[d] + b_j[d]) * W2[d,:] + b2 )
// 64x64 pair tiles, 4i x 4j per thread, float4 smem reads, MUFU gelu
// =====================================================================
__global__ __launch_bounds__(256, 2) void pair_kernel(const float* __restrict__ W2,
                                                      const float* __restrict__ b2,
                                                      float* __restrict__ out)
{
    __shared__ __align__(16) float As[64][68];
    __shared__ __align__(16) float Bs[64][68];
    __shared__ float w2s[D * 3];
    __shared__ float b2s[3];

    int tid = threadIdx.x;
    int tx = tid & 15;          // j = j0 + tx + 16*cj
    int ty = tid >> 4;          // i = i0 + ty*4 + ri
    int i0 = blockIdx.y * 64;
    int j0 = blockIdx.x * 64;

    for (int idx = tid; idx < D * 3; idx += 256) w2s[idx] = W2[idx];
    if (tid < 3) b2s[tid] = b2[tid];

    float acc[4][4][3];
#pragma unroll
    for (int a = 0; a < 4; a++)
#pragma unroll
        for (int b = 0; b < 4; b++)
#pragma unroll
            for (int c = 0; c < 3; c++) acc[a][b][c] = 0.0f;

    for (int kc = 0; kc < D; kc += 64) {
#pragma unroll
        for (int it = 0; it < 4; it++) {
            int f = tid + it * 256;
            int r = f >> 4, c4 = f & 15;
            *(float4*)&As[r][c4 * 4] = *(const float4*)&g_A[(i0 + r) * D + kc + c4 * 4];
            *(float4*)&Bs[r][c4 * 4] = *(const float4*)&g_B[(j0 + r) * D + kc + c4 * 4];
        }
        __syncthreads();

#pragma unroll 1
        for (int k4 = 0; k4 < 16; k4++) {
            float a_[4][4], b_[4][4];
#pragma unroll
            for (int ri = 0; ri < 4; ri++) {
                float4 v = *(const float4*)&As[ty * 4 + ri][k4 * 4];
                a_[ri][0] = v.x; a_[ri][1] = v.y; a_[ri][2] = v.z; a_[ri][3] = v.w;
            }
#pragma unroll
            for (int cj = 0; cj < 4; cj++) {
                float4 v = *(const float4*)&Bs[tx + cj * 16][k4 * 4];
                b_[cj][0] = v.x; b_[cj][1] = v.y; b_[cj][2] = v.z; b_[cj][3] = v.w;
            }
#pragma unroll
            for (int kk = 0; kk < 4; kk++) {
                int d = kc + k4 * 4 + kk;
                float w0  = w2s[d * 3 + 0];
                float w1  = w2s[d * 3 + 1];
                float w2v = w2s[d * 3 + 2];
#pragma unroll
                for (int ri = 0; ri < 4; ri++) {
#pragma unroll
                    for (int cj = 0; cj < 4; cj++) {
                        float g = gelu_fast(a_[ri][kk] + b_[cj][kk]);
                        acc[ri][cj][0] = fmaf(g, w0,  acc[ri][cj][0]);
                        acc[ri][cj][1] = fmaf(g, w1,  acc[ri][cj][1]);
                        acc[ri][cj][2] = fmaf(g, w2v, acc[ri][cj][2]);
                    }
                }
            }
        }
        __syncthreads();
    }

    const size_t OFF = (size_t)N * N;
#pragma unroll
    for (int ri = 0; ri < 4; ri++) {
        int i = i0 + ty * 4 + ri;
#pragma unroll
        for (int cj = 0; cj < 4; cj++) {
            int j = j0 + tx + cj * 16;
            float l0 = acc[ri][cj][0] + b2s[0];
            float l1 = acc[ri][cj][1] + b2s[1];
            float l2 = acc[ri][cj][2] + b2s[2];
            float mm = fmaxf(l0, fmaxf(l1, l2));
            float e0 = __expf(l0 - mm);
            float e1 = __expf(l1 - mm);
            float e2 = __expf(l2 - mm);
            float inv = __fdividef(1.0f, e0 + e1 + e2);
            size_t base = OFF + ((size_t)i * N + j) * 3;
            out[base + 0] = e0 * inv;
            out[base + 1] = e1 * inv;
            out[base + 2] = e2 * inv;
        }
    }
}

// =====================================================================
// launch
// =====================================================================
extern "C" void kernel_launch(void* const* d_in, const int* in_sizes, int n_in,
                              void* d_out, int out_size)
{
    const float* z   = (const float*)d_in[0];
    const float* sd  = (const float*)d_in[1];
    const float* Wq  = (const float*)d_in[2];
    const float* bq  = (const float*)d_in[3];
    const float* Wk  = (const float*)d_in[4];
    const float* bk  = (const float*)d_in[5];
    const float* W1  = (const float*)d_in[6];
    const float* b1  = (const float*)d_in[7];
    const float* W2  = (const float*)d_in[8];
    const float* b2  = (const float*)d_in[9];
    float* out = (float*)d_out;

    (void)in_sizes; (void)n_in; (void)out_size;

    proj_fused_kernel<<<dim3(8, 16), 256>>>(z, Wq, bq, Wk, bk, W1, b1);

    attn_kernel<<<dim3(16, 16), 256>>>(sd);
    softmax_topk_kernel<<<N, 256>>>(out);              // adjacency -> out[0 : N*N]

    pair_kernel<<<dim3(16, 16), 256>>>(W2, b2, out);   // signaling -> out[N*N : 4*N*N]
}

// round 3
// speedup vs baseline: 2.6507x; 1.0904x over previous
#include <cuda_runtime.h>
#include <math.h>

#define N 1024
#define D 128
#define SPARSE_K 32

typedef unsigned long long u64;

// ---------------- device scratch (no allocations allowed) ----------------
__device__ float g_Q[N * D];
__device__ float g_K[N * D];
__device__ float g_A[N * D];   // z @ W1[:D] + b1   (b1 folded here)
__device__ float g_B[N * D];   // z @ W1[D:]
__device__ float g_S[(size_t)N * N];

__device__ __forceinline__ float neg_inf() { return __int_as_float(0xff800000); }

// ---------------- packed f32x2 helpers (FFMA2 path, PTX-only) ----------------
__device__ __forceinline__ u64 pk2(float lo, float hi) {
    u64 r; asm("mov.b64 %0, {%1, %2};" : "=l"(r) : "f"(lo), "f"(hi)); return r;
}
__device__ __forceinline__ void upk2(float& lo, float& hi, u64 v) {
    asm("mov.b64 {%0, %1}, %2;" : "=f"(lo), "=f"(hi) : "l"(v));
}
__device__ __forceinline__ u64 fma2(u64 a, u64 b, u64 c) {
    u64 r; asm("fma.rn.f32x2 %0, %1, %2, %3;" : "=l"(r) : "l"(a), "l"(b), "l"(c)); return r;
}
__device__ __forceinline__ u64 add2(u64 a, u64 b) {
    u64 r; asm("add.rn.f32x2 %0, %1, %2;" : "=l"(r) : "l"(a), "l"(b)); return r;
}
__device__ __forceinline__ u64 mul2(u64 a, u64 b) {
    u64 r; asm("mul.rn.f32x2 %0, %1, %2;" : "=l"(r) : "l"(a), "l"(b)); return r;
}
__device__ __forceinline__ float tanh_hw(float x) {
    float t; asm("tanh.approx.f32 %0, %1;" : "=f"(t) : "f"(x)); return t;
}

// =====================================================================
// Kernel 1 (fused): [Q | K | A | B] = z @ [Wq | Wk | W1a | W1b] (+ bias)
// =====================================================================
__global__ __launch_bounds__(256) void proj_fused_kernel(
    const float* __restrict__ z,
    const float* __restrict__ Wq, const float* __restrict__ bq,
    const float* __restrict__ Wk, const float* __restrict__ bk,
    const float* __restrict__ W1, const float* __restrict__ b1)
{
    __shared__ __align__(16) float Zs[64][68];
    __shared__ __align__(16) float Ws[64][68];

    int ct = blockIdx.x;           // 0..7
    int which = ct >> 1;
    int j0 = (ct & 1) * 64;
    int i0 = blockIdx.y * 64;

    const float* W; const float* bias; float* out;
    if (which == 0)      { W = Wq;         bias = bq;      out = g_Q; }
    else if (which == 1) { W = Wk;         bias = bk;      out = g_K; }
    else if (which == 2) { W = W1;         bias = b1;      out = g_A; }
    else                 { W = W1 + D * D; bias = nullptr; out = g_B; }

    int tid = threadIdx.x;
    int tx = tid & 15;
    int ty = tid >> 4;

    float acc[4][4];
#pragma unroll
    for (int a = 0; a < 4; a++)
#pragma unroll
        for (int b = 0; b < 4; b++) acc[a][b] = 0.0f;

    for (int kc = 0; kc < D; kc += 64) {
#pragma unroll
        for (int it = 0; it < 4; it++) {
            int f = tid + it * 256;
            int r = f >> 4, c4 = f & 15;
            *(float4*)&Zs[r][c4 * 4] = *(const float4*)&z[(i0 + r) * D + kc + c4 * 4];
            *(float4*)&Ws[r][c4 * 4] = *(const float4*)&W[(kc + r) * D + j0 + c4 * 4];
        }
        __syncthreads();
#pragma unroll 8
        for (int k = 0; k < 64; k++) {
            float av[4], bv[4];
#pragma unroll
            for (int ri = 0; ri < 4; ri++) av[ri] = Zs[ty * 4 + ri][k];
#pragma unroll
            for (int cj = 0; cj < 4; cj++) bv[cj] = Ws[k][tx + cj * 16];
#pragma unroll
            for (int ri = 0; ri < 4; ri++)
#pragma unroll
                for (int cj = 0; cj < 4; cj++)
                    acc[ri][cj] = fmaf(av[ri], bv[cj], acc[ri][cj]);
        }
        __syncthreads();
    }

    float bb[4] = {0.f, 0.f, 0.f, 0.f};
    if (bias) {
#pragma unroll
        for (int cj = 0; cj < 4; cj++) bb[cj] = bias[j0 + tx + cj * 16];
    }
#pragma unroll
    for (int ri = 0; ri < 4; ri++) {
        int row = i0 + ty * 4 + ri;
#pragma unroll
        for (int cj = 0; cj < 4; cj++)
            out[row * D + j0 + tx + cj * 16] = acc[ri][cj] + bb[cj];
    }
}

// =====================================================================
// Kernel 2: S[i][j] = (Q_i . K_j) * (1/sqrt(D)) * exp(-sd[i][j])
// =====================================================================
__global__ __launch_bounds__(256) void attn_kernel(const float* __restrict__ sd)
{
    __shared__ __align__(16) float Qs[64][68];
    __shared__ __align__(16) float Ks[64][68];

    int tid = threadIdx.x;
    int tx = tid & 15;
    int ty = tid >> 4;
    int i0 = blockIdx.y * 64;
    int j0 = blockIdx.x * 64;

    float acc[4][4];
#pragma unroll
    for (int a = 0; a < 4; a++)
#pragma unroll
        for (int b = 0; b < 4; b++) acc[a][b] = 0.0f;

    for (int kc = 0; kc < D; kc += 64) {
#pragma unroll
        for (int it = 0; it < 4; it++) {
            int f = tid + it * 256;
            int r = f >> 4, c4 = f & 15;
            *(float4*)&Qs[r][c4 * 4] = *(const float4*)&g_Q[(i0 + r) * D + kc + c4 * 4];
            *(float4*)&Ks[r][c4 * 4] = *(const float4*)&g_K[(j0 + r) * D + kc + c4 * 4];
        }
        __syncthreads();
#pragma unroll 8
        for (int k = 0; k < 64; k++) {
            float qv[4], kv[4];
#pragma unroll
            for (int ri = 0; ri < 4; ri++) qv[ri] = Qs[ty * 4 + ri][k];
#pragma unroll
            for (int cj = 0; cj < 4; cj++) kv[cj] = Ks[tx + cj * 16][k];
#pragma unroll
            for (int ri = 0; ri < 4; ri++)
#pragma unroll
                for (int cj = 0; cj < 4; cj++)
                    acc[ri][cj] = fmaf(qv[ri], kv[cj], acc[ri][cj]);
        }
        __syncthreads();
    }

    const float SCALE = 0.08838834764831845f;  // 1/sqrt(128) / TEMPERATURE
#pragma unroll
    for (int ri = 0; ri < 4; ri++) {
        int i = i0 + ty * 4 + ri;
#pragma unroll
        for (int cj = 0; cj < 4; cj++) {
            int j = j0 + tx + cj * 16;
            size_t idx = (size_t)i * N + j;
            g_S[idx] = acc[ri][cj] * SCALE * __expf(-sd[idx]);
        }
    }
}

// =====================================================================
// Kernel 3: row softmax + top-32 scatter -> adjacency (d_out[0 : N*N])
// hierarchical top-k: per-warp extraction (no barriers) + warp-0 merge
// =====================================================================
__device__ __forceinline__ float warp_max(float x) {
#pragma unroll
    for (int o = 16; o; o >>= 1) x = fmaxf(x, __shfl_xor_sync(0xffffffffu, x, o));
    return x;
}

__global__ __launch_bounds__(256) void softmax_topk_kernel(float* __restrict__ out_adj)
{
    __shared__ float red[9];
    __shared__ float cand[256];     // 8 warps x 32 candidates
    __shared__ float s_thresh;

    int row = blockIdx.x;
    int tid = threadIdx.x;
    int w = tid >> 5, l = tid & 31;
    const float* s = g_S + (size_t)row * N;

    float v[4];
#pragma unroll
    for (int q = 0; q < 4; q++) v[q] = s[tid + q * 256];

    // --- block max ---
    float m = warp_max(fmaxf(fmaxf(v[0], v[1]), fmaxf(v[2], v[3])));
    if (l == 0) red[w] = m;
    __syncthreads();
    if (tid < 32) {
        float y = (l < 8) ? red[l] : neg_inf();
        y = warp_max(y);
        if (l == 0) red[8] = y;
    }
    __syncthreads();
    m = red[8];

    // --- exp + block sum ---
    float p[4], ls = 0.0f;
#pragma unroll
    for (int q = 0; q < 4; q++) { p[q] = __expf(v[q] - m); ls += p[q]; }
#pragma unroll
    for (int o = 16; o; o >>= 1) ls += __shfl_xor_sync(0xffffffffu, ls, o);
    if (l == 0) red[w] = ls;
    __syncthreads();
    float Z;
    if (tid < 32) {
        float y = (l < 8) ? red[l] : 0.0f;
#pragma unroll
        for (int o = 4; o; o >>= 1) y += __shfl_xor_sync(0xffffffffu, y, o);
        if (l == 0) red[8] = y;
    }
    __syncthreads();
    Z = red[8];

    // --- per-warp top-32 extraction (barrier-free) ---
    float ww[4];
#pragma unroll
    for (int q = 0; q < 4; q++) ww[q] = v[q];
    for (int it = 0; it < SPARSE_K; it++) {
        float lm = fmaxf(fmaxf(ww[0], ww[1]), fmaxf(ww[2], ww[3]));
        float gm = warp_max(lm);
#pragma unroll
        for (int q = 0; q < 4; q++) if (ww[q] == gm) ww[q] = neg_inf();
        if (l == 0) cand[w * 32 + it] = gm;
    }
    __syncthreads();

    // --- warp 0 merges 256 candidates, extracts global 32nd ---
    if (tid < 32) {
        float c[8];
#pragma unroll
        for (int q = 0; q < 8; q++) c[q] = cand[l + q * 32];
        float gm = neg_inf();
        for (int it = 0; it < SPARSE_K; it++) {
            float lm = c[0];
#pragma unroll
            for (int q = 1; q < 8; q++) lm = fmaxf(lm, c[q]);
            gm = warp_max(lm);
#pragma unroll
            for (int q = 0; q < 8; q++) if (c[q] == gm) c[q] = neg_inf();
        }
        if (l == 0) s_thresh = gm;
    }
    __syncthreads();
    float thresh = s_thresh;

    float invZ = __fdividef(1.0f, Z);
#pragma unroll
    for (int q = 0; q < 4; q++) {
        int j = tid + q * 256;
        out_adj[(size_t)row * N + j] = (v[q] >= thresh) ? p[q] * invZ : 0.0f;
    }
}

// =====================================================================
// Kernel 4 (dominant): packed-f32x2 pair classifier
//   signaling[i][j][:] = softmax( sum_d gelu(a_i[d]+b_j[d]) * W2[d,:] + b2 )
// gelu via tanh MUFU; 0.5 factor folded into pre-halved W2 in smem.
// Accumulators packed over cj pairs: lo=cj even, hi=cj odd.
// =====================================================================
__global__ __launch_bounds__(256, 2) void pair_kernel(const float* __restrict__ W2,
                                                      const float* __restrict__ b2,
                                                      float* __restrict__ out)
{
    __shared__ __align__(16) float As[64][68];
    __shared__ __align__(16) float Bs[64][68];
    __shared__ float w2s[D * 3];   // pre-halved
    __shared__ float b2s[3];

    int tid = threadIdx.x;
    int tx = tid & 15;          // j = j0 + tx + cj*16
    int ty = tid >> 4;          // i = i0 + ty*4 + ri
    int i0 = blockIdx.y * 64;
    int j0 = blockIdx.x * 64;

    for (int idx = tid; idx < D * 3; idx += 256) w2s[idx] = 0.5f * W2[idx];
    if (tid < 3) b2s[tid] = b2[tid];

    const u64 C0 = pk2(0.7978845608028654f, 0.7978845608028654f);
    const u64 C1 = pk2(0.035677408136300125f, 0.035677408136300125f); // 0.7978845608*0.044715

    u64 acc[4][2][3];
#pragma unroll
    for (int a = 0; a < 4; a++)
#pragma unroll
        for (int b = 0; b < 2; b++)
#pragma unroll
            for (int c = 0; c < 3; c++) acc[a][b][c] = 0ull;

    for (int kc = 0; kc < D; kc += 64) {
#pragma unroll
        for (int it = 0; it < 4; it++) {
            int f = tid + it * 256;
            int r = f >> 4, c4 = f & 15;
            *(float4*)&As[r][c4 * 4] = *(const float4*)&g_A[(i0 + r) * D + kc + c4 * 4];
            *(float4*)&Bs[r][c4 * 4] = *(const float4*)&g_B[(j0 + r) * D + kc + c4 * 4];
        }
        __syncthreads();

#pragma unroll 1
        for (int k4 = 0; k4 < 16; k4++) {
            float a_[4][4], b_[4][4];
#pragma unroll
            for (int ri = 0; ri < 4; ri++) {
                float4 t = *(const float4*)&As[ty * 4 + ri][k4 * 4];
                a_[ri][0] = t.x; a_[ri][1] = t.y; a_[ri][2] = t.z; a_[ri][3] = t.w;
            }
#pragma unroll
            for (int cj = 0; cj < 4; cj++) {
                float4 t = *(const float4*)&Bs[tx + cj * 16][k4 * 4];
                b_[cj][0] = t.x; b_[cj][1] = t.y; b_[cj][2] = t.z; b_[cj][3] = t.w;
            }
#pragma unroll
            for (int kk = 0; kk < 4; kk++) {
                int d = kc + k4 * 4 + kk;
                float w0 = w2s[d * 3 + 0];
                float w1 = w2s[d * 3 + 1];
                float w2v = w2s[d * 3 + 2];
                u64 w0_2 = pk2(w0, w0);
                u64 w1_2 = pk2(w1, w1);
                u64 w2_2 = pk2(w2v, w2v);
                u64 bp[2];
                bp[0] = pk2(b_[0][kk], b_[1][kk]);
                bp[1] = pk2(b_[2][kk], b_[3][kk]);
#pragma unroll
                for (int ri = 0; ri < 4; ri++) {
                    u64 a2 = pk2(a_[ri][kk], a_[ri][kk]);
#pragma unroll
                    for (int pj = 0; pj < 2; pj++) {
                        u64 x2 = add2(a2, bp[pj]);
                        u64 u2 = mul2(x2, x2);
                        u64 q2 = fma2(C1, u2, C0);
                        u64 y2 = mul2(x2, q2);
                        float ylo, yhi;
                        upk2(ylo, yhi, y2);
                        u64 t2 = pk2(tanh_hw(ylo), tanh_hw(yhi));
                        u64 g2 = fma2(x2, t2, x2);   // = 2*gelu(x); W2 pre-halved
                        acc[ri][pj][0] = fma2(g2, w0_2, acc[ri][pj][0]);
                        acc[ri][pj][1] = fma2(g2, w1_2, acc[ri][pj][1]);
                        acc[ri][pj][2] = fma2(g2, w2_2, acc[ri][pj][2]);
                    }
                }
            }
        }
        __syncthreads();
    }

    const size_t OFF = (size_t)N * N;
#pragma unroll
    for (int ri = 0; ri < 4; ri++) {
        int i = i0 + ty * 4 + ri;
#pragma unroll
        for (int pj = 0; pj < 2; pj++) {
            float l0a, l0b, l1a, l1b, l2a, l2b;
            upk2(l0a, l0b, acc[ri][pj][0]);
            upk2(l1a, l1b, acc[ri][pj][1]);
            upk2(l2a, l2b, acc[ri][pj][2]);
#pragma unroll
            for (int h = 0; h < 2; h++) {
                int cj = pj * 2 + h;
                int j = j0 + tx + cj * 16;
                float l0 = (h ? l0b : l0a) + b2s[0];
                float l1 = (h ? l1b : l1a) + b2s[1];
                float l2 = (h ? l2b : l2a) + b2s[2];
                float mm = fmaxf(l0, fmaxf(l1, l2));
                float e0 = __expf(l0 - mm);
                float e1 = __expf(l1 - mm);
                float e2 = __expf(l2 - mm);
                float inv = __fdividef(1.0f, e0 + e1 + e2);
                size_t base = OFF + ((size_t)i * N + j) * 3;
                out[base + 0] = e0 * inv;
                out[base + 1] = e1 * inv;
                out[base + 2] = e2 * inv;
            }
        }
    }
}

// =====================================================================
// launch
// =====================================================================
extern "C" void kernel_launch(void* const* d_in, const int* in_sizes, int n_in,
                              void* d_out, int out_size)
{
    const float* z   = (const float*)d_in[0];
    const float* sd  = (const float*)d_in[1];
    const float* Wq  = (const float*)d_in[2];
    const float* bq  = (const float*)d_in[3];
    const float* Wk  = (const float*)d_in[4];
    const float* bk  = (const float*)d_in[5];
    const float* W1  = (const float*)d_in[6];
    const float* b1  = (const float*)d_in[7];
    const float* W2  = (const float*)d_in[8];
    const float* b2  = (const float*)d_in[9];
    float* out = (float*)d_out;

    (void)in_sizes; (void)n_in; (void)out_size;

    proj_fused_kernel<<<dim3(8, 16), 256>>>(z, Wq, bq, Wk, bk, W1, b1);

    attn_kernel<<<dim3(16, 16), 256>>>(sd);
    softmax_topk_kernel<<<N, 256>>>(out);              // adjacency -> out[0 : N*N]

    pair_kernel<<<dim3(16, 16), 256>>>(W2, b2, out);   // signaling -> out[N*N : 4*N*N]
}